// round 9
// baseline (speedup 1.0000x reference)
#include <cuda_runtime.h>
#include <cuda_bf16.h>
#include <cstdint>
#include <math.h>

// NT-Xent loss, N=4096, D=256, T=0.5. bf16 mma.sync m16n8k16, upper-triangle,
// mbarrier-pipelined persistent kernel, 256 threads (2x4 warps, 64x32 warp
// tile), CROSS-TILE PIPELINED EPILOGUE: tile i's k-loop interleaves the
// exp-sum of tile i-1 (MUFU hides under tensor). Fused final reduction.

#define NROW 8192
#define NHALF 4096
#define DIM 256
#define NTILE 64
#define TOTAL_UT 2080               // 64*65/2
#define C2 2.885390081777927f       // 2 * log2(e)
#define NB 148

// smem: swizzled 512B-row bf16 tiles (64KB each): A + B0 + B1 + mbarriers
#define SM_A 0
#define SM_B0 65536
#define SM_B1 131072
#define SM_BAR 196608
#define SMEM_TOTAL (196608 + 64)

__device__ __nv_bfloat16 g_zh[NROW * DIM];
__device__ float g_denom[NROW];
__device__ float g_pos[NHALF];
__device__ float g_self[NROW];
__device__ unsigned int g_done;

// ---------------------------------------------------------------------------
__device__ __forceinline__ float ex2f(float x) {
    float y; asm("ex2.approx.ftz.f32 %0, %1;" : "=f"(y) : "f"(x)); return y;
}
__device__ __forceinline__ uint32_t smem_u32(const void* p) {
    uint32_t a;
    asm("{ .reg .u64 t; cvta.to.shared.u64 t, %1; cvt.u32.u64 %0, t; }"
        : "=r"(a) : "l"(p));
    return a;
}
__device__ __forceinline__ void cp16(uint32_t s, const void* g) {
    asm volatile("cp.async.cg.shared.global [%0], [%1], 16;" :: "r"(s), "l"(g));
}
#define CP_COMMIT() asm volatile("cp.async.commit_group;" ::: "memory")
#define CP_WAIT0()  asm volatile("cp.async.wait_group 0;" ::: "memory")

#define MBAR_INIT(a, c) \
    asm volatile("mbarrier.init.shared.b64 [%0], %1;" :: "r"(a), "r"(c) : "memory")
#define MBAR_INVAL(a) \
    asm volatile("mbarrier.inval.shared.b64 [%0];" :: "r"(a) : "memory")
#define MBAR_ARRIVE(a) \
    asm volatile("mbarrier.arrive.shared.b64 _, [%0];" :: "r"(a) : "memory")
#define CPA_NOINC(a) \
    asm volatile("cp.async.mbarrier.arrive.noinc.shared.b64 [%0];" :: "r"(a) : "memory")

#define MBAR_WAIT(mbar, ph) do {                                              \
    uint32_t _m = (mbar); uint32_t _p = (uint32_t)(ph); uint32_t _done;       \
    asm volatile("{\n\t.reg .pred p;\n\t"                                     \
        "mbarrier.try_wait.parity.shared.b64 p, [%1], %2;\n\t"                \
        "selp.b32 %0, 1, 0, p;\n\t}"                                          \
        : "=r"(_done) : "r"(_m), "r"(_p) : "memory");                         \
    if (!_done) {                                                             \
        asm volatile("{\n\t.reg .pred P1;\n\t"                                \
            "WL_%=:\n\t"                                                      \
            "mbarrier.try_wait.parity.shared.b64 P1, [%0], %1;\n\t"           \
            "@P1 bra.uni WD_%=;\n\t"                                          \
            "bra.uni WL_%=;\n\t"                                              \
            "WD_%=:\n\t}" :: "r"(_m), "r"(_p) : "memory");                    \
    }                                                                         \
} while (0)

#define LDSM4(r0, r1, r2, r3, a)                                        \
    asm volatile("ldmatrix.sync.aligned.m8n8.x4.shared.b16 "            \
                 "{%0,%1,%2,%3}, [%4];"                                 \
                 : "=r"(r0), "=r"(r1), "=r"(r2), "=r"(r3) : "r"(a))

#define MMA16816(c, a, b0, b1)                                          \
    asm volatile("mma.sync.aligned.m16n8k16.row.col.f32.bf16.bf16.f32 " \
                 "{%0,%1,%2,%3}, {%4,%5,%6,%7}, {%8,%9}, {%0,%1,%2,%3};"\
                 : "+f"((c)[0]), "+f"((c)[1]), "+f"((c)[2]), "+f"((c)[3]) \
                 : "r"((a)[0]), "r"((a)[1]), "r"((a)[2]), "r"((a)[3]),  \
                   "r"(b0), "r"(b1))

// ---------------------------------------------------------------------------
// Kernel 1: normalize (warp per row); bf16 z, self-sim, fp32 positives.
// ---------------------------------------------------------------------------
__global__ void norm_pos_kernel(const float* __restrict__ ei,
                                const float* __restrict__ ej) {
    const int tid = threadIdx.x, w = tid >> 5, lane = tid & 31;
    const int half = w >> 2;
    const int k = blockIdx.x * 4 + (w & 3);
    const int row = k + half * NHALF;
    const float* src = (half ? ej : ei) + (size_t)k * DIM + lane * 8;

    if (blockIdx.x == 0 && tid == 0) g_done = 0;

    float4 v0 = *reinterpret_cast<const float4*>(src);
    float4 v1 = *reinterpret_cast<const float4*>(src + 4);
    float vf[8] = {v0.x, v0.y, v0.z, v0.w, v1.x, v1.y, v1.z, v1.w};

    float s = 0.f;
    #pragma unroll
    for (int i = 0; i < 8; i++) s += vf[i] * vf[i];
    #pragma unroll
    for (int o = 16; o; o >>= 1) s += __shfl_xor_sync(~0u, s, o);
    const float inv = 1.0f / fmaxf(sqrtf(s), 1e-8f);

    float zf[8];
    __nv_bfloat162 zb[4];
    float ss = 0.f;
    #pragma unroll
    for (int i = 0; i < 8; i++) zf[i] = vf[i] * inv;
    #pragma unroll
    for (int i = 0; i < 4; i++) {
        zb[i] = __floats2bfloat162_rn(zf[2 * i], zf[2 * i + 1]);
        float lo = __bfloat162float(zb[i].x), hi = __bfloat162float(zb[i].y);
        ss += lo * lo + hi * hi;
    }
    *reinterpret_cast<uint4*>(&g_zh[(size_t)row * DIM + lane * 8]) =
        *reinterpret_cast<uint4*>(zb);
    #pragma unroll
    for (int o = 16; o; o >>= 1) ss += __shfl_xor_sync(~0u, ss, o);
    if (lane == 0) { g_self[row] = ss; g_denom[row] = 0.f; }

    __shared__ float zsh[4][DIM];
    if (half == 0) {
        #pragma unroll
        for (int i = 0; i < 8; i++) zsh[w & 3][lane * 8 + i] = zf[i];
    }
    __syncthreads();
    if (half == 1) {
        float p = 0.f;
        #pragma unroll
        for (int i = 0; i < 8; i++) p += zsh[w & 3][lane * 8 + i] * zf[i];
        #pragma unroll
        for (int o = 16; o; o >>= 1) p += __shfl_xor_sync(~0u, p, o);
        if (lane == 0) g_pos[k] = p;
    }
}

// ---------------------------------------------------------------------------
// cp.async of a 128x256 bf16 tile into 512B-row smem, 16B-chunk XOR swizzle.
// 256 threads, 16 chunks each. No commit here.
// ---------------------------------------------------------------------------
__device__ __forceinline__ void fill_tile(uint32_t sdst, int zrow, int tid) {
    const __nv_bfloat16* src = g_zh + ((size_t)zrow << 8);
    #pragma unroll
    for (int i = 0; i < 16; ++i) {
        int q = tid + (i << 8);          // 16B chunk id 0..4095
        int r = q >> 5;                  // row 0..127
        int c = q & 31;
        cp16(sdst + (r << 9) + ((c ^ (r & 7)) << 4), src + ((size_t)q << 3));
    }
}

// ---------------------------------------------------------------------------
// k-loop for one tile with interleaved fold of the PREVIOUS tile's epilogue.
// All indices constant after unroll -> arrays stay in registers.
// ---------------------------------------------------------------------------
__device__ __forceinline__ void ktile(
    uint32_t aBase, uint32_t bBase,
    const uint32_t (&aRow)[4], uint32_t bRow0, uint32_t bRow1,
    uint32_t hiA, uint32_t hiB, uint32_t rm,
    float (&acc)[4][4][4], float (&prev)[4][4][4],
    float (&dacc)[4][2], float (&colacc)[4][2]) {
    #pragma unroll
    for (int x = 0; x < 4; x++) {
        colacc[x][0] = 0.f; colacc[x][1] = 0.f;
        #pragma unroll
        for (int y = 0; y < 4; y++)
            #pragma unroll
            for (int c = 0; c < 4; c++) acc[x][y][c] = 0.f;
    }
    #pragma unroll
    for (int s = 0; s < 16; ++s) {
        const uint32_t offA = (((uint32_t)s << 5) + hiA) ^ rm;
        const uint32_t offB = (((uint32_t)s << 5) + hiB) ^ rm;
        uint32_t a[4][4];
        #pragma unroll
        for (int mf = 0; mf < 4; ++mf)
            LDSM4(a[mf][0], a[mf][1], a[mf][2], a[mf][3],
                  aBase + aRow[mf] + offA);
        uint32_t bq[2][4];
        LDSM4(bq[0][0], bq[0][1], bq[0][2], bq[0][3], bBase + bRow0 + offB);
        LDSM4(bq[1][0], bq[1][1], bq[1][2], bq[1][3], bBase + bRow1 + offB);
        #pragma unroll
        for (int mf = 0; mf < 4; ++mf)
            #pragma unroll
            for (int nf = 0; nf < 4; ++nf)
                MMA16816(acc[mf][nf], a[mf],
                         bq[nf >> 1][(nf & 1) * 2],
                         bq[nf >> 1][(nf & 1) * 2 + 1]);
        // fold 4 elements of previous tile's epilogue (hides under tensor)
        #pragma unroll
        for (int j = 0; j < 4; ++j) {
            const int e = s * 4 + j;
            const int mf = e >> 4, nf = (e >> 2) & 3, c = e & 3;
            float ev = ex2f(prev[mf][nf][c] * C2);
            dacc[mf][c >> 1] += ev;
            colacc[nf][c & 1] += ev;
        }
    }
}

// ---------------------------------------------------------------------------
// Kernel 2: persistent upper-tri sim-GEMM + pipelined exp-sum + fused finish.
// 148 CTAs x 256 threads; 8 warps = 2(M) x 4(N); warp tile 64x32.
// ---------------------------------------------------------------------------
__global__ __launch_bounds__(256, 1) void sim_kernel(float* __restrict__ out) {
    extern __shared__ char smem[];
    const uint32_t sb = smem_u32(smem);
    const uint32_t FULL[2]  = {sb + SM_BAR,      sb + SM_BAR + 8};
    const uint32_t EMPTY[2] = {sb + SM_BAR + 16, sb + SM_BAR + 24};
    const uint32_t BUF[2]   = {sb + SM_B0, sb + SM_B1};
    const int tid = threadIdx.x, wid = tid >> 5, lane = tid & 31;
    const int wm = wid >> 2, wn = wid & 3;

    const int b = blockIdx.x, nb = gridDim.x;
    const int t0 = (b * TOTAL_UT) / nb;
    const int t1 = ((b + 1) * TOTAL_UT) / nb;
    const int nt = t1 - t0;

    int R = 0, rem = t0;
    while (rem >= NTILE - R) { rem -= NTILE - R; R++; }
    int C = R + rem;

    if (tid == 0) {
        MBAR_INIT(FULL[0], 256); MBAR_INIT(FULL[1], 256);
        MBAR_INIT(EMPTY[0], 256); MBAR_INIT(EMPTY[1], 256);
    }
    __syncthreads();

    const uint32_t rm  = (uint32_t)(lane & 7) << 4;
    const uint32_t hiA = (uint32_t)(lane >> 4) << 4;
    const uint32_t hiB = (uint32_t)((lane >> 3) & 1) << 4;
    uint32_t aRow[4];
    #pragma unroll
    for (int mf = 0; mf < 4; ++mf)
        aRow[mf] = (uint32_t)(wm * 64 + mf * 16 + (lane & 15)) << 9;
    const uint32_t rB0 = (uint32_t)(wn * 32 + (lane & 7) + ((lane >> 4) << 3));
    const uint32_t bRow0 = rB0 << 9, bRow1 = (rB0 + 16) << 9;

    float dacc[4][2];
    float colacc[4][2];
    float acc0[4][4][4], acc1[4][4][4];
    #pragma unroll
    for (int x = 0; x < 4; x++) {
        dacc[x][0] = 0.f; dacc[x][1] = 0.f;
        #pragma unroll
        for (int y = 0; y < 4; y++)
            #pragma unroll
            for (int c = 0; c < 4; c++) acc1[x][y][c] = -1e30f;  // ex2->0
    }

    int loadedR = R;
    int pR = R, pC = C;
    bool pOff = false;                   // first fold: no colacc flush
    fill_tile(sb + SM_A, R << 7, tid);
    fill_tile(BUF[0], C << 7, tid);
    CPA_NOINC(FULL[0]);
    CP_COMMIT(); CP_WAIT0();
    __syncthreads();

    for (int i = 0; i < nt; ++i) {
        int Rn = R, Cn = C + 1;
        if (Cn == NTILE) { Rn = R + 1; Cn = Rn; }

        if (R != loadedR) {              // A reload (dacc flushed below,
            __syncthreads();             //  after the pending fold completes)
            fill_tile(sb + SM_A, R << 7, tid);
            CP_COMMIT(); CP_WAIT0();
            __syncthreads();
            loadedR = R;
        }

        if (i + 1 < nt) {
            const int nbuf = (i + 1) & 1;
            if (i + 1 >= 2)
                MBAR_WAIT(EMPTY[nbuf], ((((i + 1) >> 1) - 1) & 1));
            fill_tile(BUF[nbuf], Cn << 7, tid);
            CPA_NOINC(FULL[nbuf]);
        }

        const int cb = i & 1;
        MBAR_WAIT(FULL[cb], (i >> 1) & 1);

        if ((i & 1) == 0)
            ktile(sb + SM_A, BUF[cb], aRow, bRow0, bRow1, hiA, hiB, rm,
                  acc0, acc1, dacc, colacc);
        else
            ktile(sb + SM_A, BUF[cb], aRow, bRow0, bRow1, hiA, hiB, rm,
                  acc1, acc0, dacc, colacc);
        MBAR_ARRIVE(EMPTY[cb]);

        // column flush for tile i-1 (folded during the k-loop above)
        if (pOff) {
            #pragma unroll
            for (int nf = 0; nf < 4; ++nf)
                #pragma unroll
                for (int p = 0; p < 2; ++p) {
                    float v = colacc[nf][p];
                    v += __shfl_xor_sync(~0u, v, 4);
                    v += __shfl_xor_sync(~0u, v, 8);
                    v += __shfl_xor_sync(~0u, v, 16);
                    if (lane < 4)
                        atomicAdd(&g_denom[(pC << 7) + wn * 32 + nf * 8
                                           + (lane & 3) * 2 + p], v);
                }
        }
        // row flush when tile i-1 closed out its row-block
        if (i > 0 && pR != R) {
            #pragma unroll
            for (int mf = 0; mf < 4; ++mf)
                #pragma unroll
                for (int h = 0; h < 2; ++h) {
                    float v = dacc[mf][h];
                    v += __shfl_xor_sync(~0u, v, 1);
                    v += __shfl_xor_sync(~0u, v, 2);
                    if ((lane & 3) == 0)
                        atomicAdd(&g_denom[(pR << 7) + wm * 64 + mf * 16
                                           + (lane >> 2) + h * 8], v);
                    dacc[mf][h] = 0.f;
                }
        }

        pR = R; pC = C; pOff = (C != R);
        R = Rn; C = Cn;
    }

    // drain: epilogue of the last tile (no interleave partner)
    {
        float (&last)[4][4][4] = ((nt - 1) & 1) ? acc1 : acc0;
        float cl[4][2];
        #pragma unroll
        for (int x = 0; x < 4; x++) { cl[x][0] = 0.f; cl[x][1] = 0.f; }
        #pragma unroll
        for (int mf = 0; mf < 4; ++mf)
            #pragma unroll
            for (int nf = 0; nf < 4; ++nf)
                #pragma unroll
                for (int c = 0; c < 4; ++c) {
                    float ev = ex2f(last[mf][nf][c] * C2);
                    dacc[mf][c >> 1] += ev;
                    cl[nf][c & 1] += ev;
                }
        if (pOff) {
            #pragma unroll
            for (int nf = 0; nf < 4; ++nf)
                #pragma unroll
                for (int p = 0; p < 2; ++p) {
                    float v = cl[nf][p];
                    v += __shfl_xor_sync(~0u, v, 4);
                    v += __shfl_xor_sync(~0u, v, 8);
                    v += __shfl_xor_sync(~0u, v, 16);
                    if (lane < 4)
                        atomicAdd(&g_denom[(pC << 7) + wn * 32 + nf * 8
                                           + (lane & 3) * 2 + p], v);
                }
        }
        #pragma unroll
        for (int mf = 0; mf < 4; ++mf)
            #pragma unroll
            for (int h = 0; h < 2; ++h) {
                float v = dacc[mf][h];
                v += __shfl_xor_sync(~0u, v, 1);
                v += __shfl_xor_sync(~0u, v, 2);
                if ((lane & 3) == 0)
                    atomicAdd(&g_denom[(pR << 7) + wm * 64 + mf * 16
                                       + (lane >> 2) + h * 8], v);
            }
    }

    __syncthreads();
    if (tid == 0) {
        MBAR_INVAL(FULL[0]); MBAR_INVAL(FULL[1]);
        MBAR_INVAL(EMPTY[0]); MBAR_INVAL(EMPTY[1]);
    }

    // ---- fused finish: last CTA reduces the scalar ----
    __shared__ unsigned int amLast;
    if (tid == 0) {
        __threadfence();
        amLast = (atomicAdd(&g_done, 1u) == (unsigned)(nb - 1)) ? 1u : 0u;
    }
    __syncthreads();
    if (amLast) {
        __threadfence();
        double s = 0.0;
        for (int r = tid; r < NROW; r += 256) {
            float denom = g_denom[r] - ex2f(g_self[r] * C2);
            int pk = (r < NHALF) ? r : (r - NHALF);
            s += (double)(__logf(denom) - 2.0f * g_pos[pk]);
        }
        #pragma unroll
        for (int o = 16; o; o >>= 1) s += __shfl_xor_sync(~0u, s, o);
        __shared__ double ws[8];
        if (lane == 0) ws[wid] = s;
        __syncthreads();
        if (tid == 0) {
            double tot = 0.0;
            #pragma unroll
            for (int i = 0; i < 8; i++) tot += ws[i];
            out[0] = (float)(tot / (double)NROW);
        }
    }
}

// ---------------------------------------------------------------------------
extern "C" void kernel_launch(void* const* d_in, const int* in_sizes, int n_in,
                              void* d_out, int out_size) {
    const float* emb_i = (const float*)d_in[0];
    const float* emb_j = (const float*)d_in[1];
    float* out = (float*)d_out;

    cudaFuncSetAttribute(sim_kernel, cudaFuncAttributeMaxDynamicSharedMemorySize,
                         SMEM_TOTAL);
    norm_pos_kernel<<<1024, 256>>>(emb_i, emb_j);
    sim_kernel<<<NB, 256, SMEM_TOTAL>>>(out);
}